// round 2
// baseline (speedup 1.0000x reference)
#include <cuda_runtime.h>
#include <math.h>

#define N_E 16384
#define NF  128
#define NM  25

// ---------------- scratch (device globals; no allocation allowed) ----------------
__device__ float g_y0[(size_t)N_E * NM * NF];   // gather output / final y
__device__ float g_y1[(size_t)N_E * NM * NF];   // post-W1 / post-mish
__device__ float g_rad[(size_t)N_E * NF];
__device__ float g_shg[(size_t)N_E * 9];
__device__ float g_v[(size_t)N_E * 3 * NF];
__device__ float g_C[23 * 729];                 // real CG tables [p][a][b][c] strides 81,9,1

__constant__ int dPL1[23]  = {0,0,0,0,0, 1,1,1,1,1,1,1,1, 2,2,2,2,2,2,2,2,2,2};
__constant__ int dPL2[23]  = {0,1,2,3,4, 0,1,1,2,2,3,3,4, 0,1,1,2,2,2,3,3,4,4};
__constant__ int dPL3[23]  = {0,1,2,3,4, 1,0,2,1,3,2,4,3, 2,1,3,0,2,4,1,3,2,4};
__constant__ int dMOFF[24] = {0,1,10,35,84,165,168,171,186,201,236,271,334,
                              397,402,411,432,437,462,507,528,577,622,703};

// ---------------- CG table computation (double, matches reference) ----------------
__device__ double factd(int n) { double r = 1.0; for (int i = 2; i <= n; ++i) r *= (double)i; return r; }

__device__ double cgc(int l1, int l2, int l3, int m1, int m2, int m3) {
    if (m1 + m2 != m3) return 0.0;
    if (l3 < abs(l1 - l2) || l3 > l1 + l2) return 0.0;
    double pre = sqrt((double)(2 * l3 + 1) * factd(l3 + l1 - l2) * factd(l3 - l1 + l2) *
                      factd(l1 + l2 - l3) / factd(l1 + l2 + l3 + 1));
    pre *= sqrt(factd(l3 + m3) * factd(l3 - m3) * factd(l1 - m1) * factd(l1 + m1) *
                factd(l2 - m2) * factd(l2 + m2));
    double s = 0.0;
    for (int k = 0; k <= l1 + l2 - l3; ++k) {
        int a0 = k, a1 = l1 + l2 - l3 - k, a2 = l1 - m1 - k, a3 = l2 + m2 - k;
        int a4 = l3 - l2 + m1 + k, a5 = l3 - l1 - m2 + k;
        if (a0 < 0 || a1 < 0 || a2 < 0 || a3 < 0 || a4 < 0 || a5 < 0) continue;
        double d = factd(a0) * factd(a1) * factd(a2) * factd(a3) * factd(a4) * factd(a5);
        s += ((k & 1) ? -1.0 : 1.0) / d;
    }
    return pre * s;
}

// U[a, A] element of the complex->real change-of-basis matrix for degree l
__device__ void u_elem(int l, int a, int A, double& re, double& im) {
    re = 0.0; im = 0.0;
    const double is2 = 0.70710678118654752440;
    int mA = A - l, ma = a - l;
    if (mA == 0) { if (ma == 0) re = 1.0; return; }
    int m = mA > 0 ? mA : -mA;
    double sgn = (m & 1) ? -1.0 : 1.0;
    if (mA > 0) {
        if (ma == m)       re = sgn * is2;   // U[l+m, l+m]
        else if (ma == -m) re = is2;         // U[l-m, l+m]
    } else {
        if (ma == m)       im = sgn * is2;   // U[l+m, l-m] = i(-1)^m/sqrt2
        else if (ma == -m) im = -is2;        // U[l-m, l-m] = -i/sqrt2
    }
}

__global__ void cg_init_kernel() {
    int p = blockIdx.x;
    int l1 = dPL1[p], l2 = dPL2[p], l3 = dPL3[p];
    int n1 = 2 * l1 + 1, n2 = 2 * l2 + 1, n3 = 2 * l3 + 1;
    int total = n1 * n2 * n3;
    for (int idx = threadIdx.x; idx < total; idx += blockDim.x) {
        int A  = idx / (n2 * n3);
        int rm = idx % (n2 * n3);
        int B  = rm / n3;
        int Cc = rm % n3;
        double acc = 0.0;
        for (int a = 0; a < n1; ++a) {
            double u1r, u1i; u_elem(l1, a, A, u1r, u1i);
            if (u1r == 0.0 && u1i == 0.0) continue;
            int m1 = a - l1;
            for (int b = 0; b < n2; ++b) {
                double u2r, u2i; u_elem(l2, b, B, u2r, u2i);
                if (u2r == 0.0 && u2i == 0.0) continue;
                int m2 = b - l2;
                int m3 = m1 + m2;
                if (m3 < -l3 || m3 > l3) continue;
                double cg = cgc(l1, l2, l3, m1, m2, m3);
                if (cg == 0.0) continue;
                int c = l3 + m3;
                double u3r, u3i; u_elem(l3, c, Cc, u3r, u3i);
                // (u1*u2) * conj(u3), take real part
                double pr = u1r * u2r - u1i * u2i;
                double pi = u1r * u2i + u1i * u2r;
                acc += cg * (pr * u3r + pi * u3i);
            }
        }
        g_C[p * 729 + A * 81 + B * 9 + Cc] = (float)acc;
    }
}

// ---------------- stage 1: gather + add ----------------
__global__ __launch_bounds__(256) void gather_kernel(const float* __restrict__ desc,
                                                     const int* __restrict__ nidx) {
    int e = blockIdx.x;
    int i = nidx[2 * e], j = nidx[2 * e + 1];
    const float4* A = reinterpret_cast<const float4*>(desc + (size_t)i * (NM * NF));
    const float4* B = reinterpret_cast<const float4*>(desc + (size_t)j * (NM * NF));
    float4* O = reinterpret_cast<float4*>(g_y0 + (size_t)e * (NM * NF));
    for (int t = threadIdx.x; t < NM * NF / 4; t += 256) {
        float4 a = A[t], b = B[t];
        float4 o; o.x = a.x + b.x; o.y = a.y + b.y; o.z = a.z + b.z; o.w = a.w + b.w;
        O[t] = o;
    }
}

// ---------------- GEMM over (E,25,F) rows with per-m weight selection ----------------
// STAGE 0: g_y1 = g_y0 @ W1 (+b1 at m==0)
// STAGE 1: g_y0 = g_y1 @ W2 (+b2 at m==0) + g_y1 (residual)
template <int STAGE>
__global__ __launch_bounds__(256) void gemm25_kernel(const float* __restrict__ Wall,
                                                     const float* __restrict__ bias) {
    const float* __restrict__ X = (STAGE == 0) ? g_y0 : g_y1;
    float* __restrict__ Y       = (STAGE == 0) ? g_y1 : g_y0;
    const int m = blockIdx.y;
    const int l = (m >= 16) ? 4 : (m >= 9) ? 3 : (m >= 4) ? 2 : (m >= 1) ? 1 : 0;
    const float* __restrict__ W = Wall + (size_t)l * NF * NF;
    const int e0 = blockIdx.x * 128;
    const int tid = threadIdx.x;
    const int tr = tid >> 4, tc = tid & 15;

    __shared__ float Xs[128 * 32];
    __shared__ float Ws[32 * 128];

    float acc[8][8];
#pragma unroll
    for (int i = 0; i < 8; ++i)
#pragma unroll
        for (int j = 0; j < 8; ++j) acc[i][j] = 0.f;

    for (int kc = 0; kc < NF; kc += 32) {
#pragma unroll
        for (int t = 0; t < 4; ++t) {
            int idx = tid + t * 256;
            int r = idx >> 3, c4 = idx & 7;
            *reinterpret_cast<float4*>(Xs + r * 32 + c4 * 4) =
                *reinterpret_cast<const float4*>(X + ((size_t)(e0 + r) * NM + m) * NF + kc + c4 * 4);
            int k = idx >> 5, g4 = idx & 31;
            *reinterpret_cast<float4*>(Ws + k * 128 + g4 * 4) =
                *reinterpret_cast<const float4*>(W + (size_t)(kc + k) * NF + g4 * 4);
        }
        __syncthreads();
#pragma unroll
        for (int k = 0; k < 32; ++k) {
            float xv[8], wv[8];
#pragma unroll
            for (int i = 0; i < 8; ++i) xv[i] = Xs[(tr * 8 + i) * 32 + k];
            *reinterpret_cast<float4*>(wv)     = *reinterpret_cast<const float4*>(Ws + k * 128 + tc * 8);
            *reinterpret_cast<float4*>(wv + 4) = *reinterpret_cast<const float4*>(Ws + k * 128 + tc * 8 + 4);
#pragma unroll
            for (int i = 0; i < 8; ++i)
#pragma unroll
                for (int j = 0; j < 8; ++j) acc[i][j] = fmaf(xv[i], wv[j], acc[i][j]);
        }
        __syncthreads();
    }

    float bvals[8];
#pragma unroll
    for (int j = 0; j < 8; ++j) bvals[j] = (m == 0) ? bias[tc * 8 + j] : 0.f;

#pragma unroll
    for (int i = 0; i < 8; ++i) {
        size_t row = ((size_t)(e0 + tr * 8 + i) * NM + m) * NF + tc * 8;
        float out[8];
#pragma unroll
        for (int j = 0; j < 8; ++j) out[j] = acc[i][j] + bvals[j];
        if (STAGE == 1) {
#pragma unroll
            for (int j = 0; j < 8; ++j) out[j] += g_y1[row + j];
        }
        *reinterpret_cast<float4*>(Y + row)     = *reinterpret_cast<const float4*>(out);
        *reinterpret_cast<float4*>(Y + row + 4) = *reinterpret_cast<const float4*>(out + 4);
    }
}

// ---------------- normalize + gated mish (in place on g_y1) ----------------
__global__ __launch_bounds__(128) void norm_mish_kernel() {
    int e = blockIdx.x, f = threadIdx.x;
    size_t base = (size_t)e * (NM * NF) + f;
    float v[NM];
    float n2 = 0.f;
#pragma unroll
    for (int m = 0; m < NM; ++m) { v[m] = g_y1[base + (size_t)m * NF]; n2 += v[m] * v[m]; }
    float sc = rsqrtf(n2 + 1e-6f);
    float s = v[0] * sc;
    float sp = fmaxf(s, 0.f) + log1pf(expf(-fabsf(s)));   // stable softplus
    float t = tanhf(sp);
    float sig = 1.f / (1.f + expf(-s));
    float dm = t + s * (1.f - t * t) * sig;
    g_y1[base] = s * t;
#pragma unroll
    for (int m = 1; m < NM; ++m) g_y1[base + (size_t)m * NF] = v[m] * sc * dm;
}

// ---------------- radial basis + spherical harmonics ----------------
__global__ __launch_bounds__(128) void radsh_kernel(const float* __restrict__ disp) {
    int e = blockIdx.x, f = threadIdx.x;
    float dx = disp[3 * e], dy = disp[3 * e + 1], dz = disp[3 * e + 2];
    float r = sqrtf(dx * dx + dy * dy + dz * dz + 1e-12f);
    float x = dx / r, y = dy / r, z = dz / r;
    float uc = r / 5.0f;
    float denom = fmaxf(1.f - uc * uc, 1e-9f);
    float cut = (uc < 1.f) ? expf(1.f - 1.f / denom) : 0.f;
    float ang = 3.14159265358979323846f * r / 5.0f;
    g_rad[(size_t)e * NF + f] = cosf((float)f * ang) * cut;
    if (f < 9) {
        const float s3 = 1.7320508075688772f;
        float shv;
        switch (f) {
            case 0: shv = 1.f; break;
            case 1: shv = y; break;
            case 2: shv = z; break;
            case 3: shv = x; break;
            case 4: shv = s3 * x * y; break;
            case 5: shv = s3 * y * z; break;
            case 6: shv = 0.5f * (3.f * z * z - 1.f); break;
            case 7: shv = s3 * x * z; break;
            default: shv = 0.5f * s3 * (x * x - y * y); break;
        }
        g_shg[(size_t)e * 9 + f] = shv;
    }
}

// ---------------- v_l = rad @ W3[l] (+b3 at l==0); rows = edges ----------------
__global__ __launch_bounds__(256) void gemmrad_kernel(const float* __restrict__ W3,
                                                      const float* __restrict__ b3) {
    const int l = blockIdx.y;
    const float* __restrict__ W = W3 + (size_t)l * NF * NF;
    const int e0 = blockIdx.x * 128;
    const int tid = threadIdx.x;
    const int tr = tid >> 4, tc = tid & 15;

    __shared__ float Xs[128 * 32];
    __shared__ float Ws[32 * 128];

    float acc[8][8];
#pragma unroll
    for (int i = 0; i < 8; ++i)
#pragma unroll
        for (int j = 0; j < 8; ++j) acc[i][j] = 0.f;

    for (int kc = 0; kc < NF; kc += 32) {
#pragma unroll
        for (int t = 0; t < 4; ++t) {
            int idx = tid + t * 256;
            int r = idx >> 3, c4 = idx & 7;
            *reinterpret_cast<float4*>(Xs + r * 32 + c4 * 4) =
                *reinterpret_cast<const float4*>(g_rad + (size_t)(e0 + r) * NF + kc + c4 * 4);
            int k = idx >> 5, g4 = idx & 31;
            *reinterpret_cast<float4*>(Ws + k * 128 + g4 * 4) =
                *reinterpret_cast<const float4*>(W + (size_t)(kc + k) * NF + g4 * 4);
        }
        __syncthreads();
#pragma unroll
        for (int k = 0; k < 32; ++k) {
            float xv[8], wv[8];
#pragma unroll
            for (int i = 0; i < 8; ++i) xv[i] = Xs[(tr * 8 + i) * 32 + k];
            *reinterpret_cast<float4*>(wv)     = *reinterpret_cast<const float4*>(Ws + k * 128 + tc * 8);
            *reinterpret_cast<float4*>(wv + 4) = *reinterpret_cast<const float4*>(Ws + k * 128 + tc * 8 + 4);
#pragma unroll
            for (int i = 0; i < 8; ++i)
#pragma unroll
                for (int j = 0; j < 8; ++j) acc[i][j] = fmaf(xv[i], wv[j], acc[i][j]);
        }
        __syncthreads();
    }

    float bvals[8];
#pragma unroll
    for (int j = 0; j < 8; ++j) bvals[j] = (l == 0) ? b3[tc * 8 + j] : 0.f;  // fold b3 into v0
#pragma unroll
    for (int i = 0; i < 8; ++i) {
        size_t row = ((size_t)(e0 + tr * 8 + i) * 3 + l) * NF + tc * 8;
        float out[8];
#pragma unroll
        for (int j = 0; j < 8; ++j) out[j] = acc[i][j] + bvals[j];
        *reinterpret_cast<float4*>(g_v + row)     = *reinterpret_cast<const float4*>(out);
        *reinterpret_cast<float4*>(g_v + row + 4) = *reinterpret_cast<const float4*>(out + 4);
    }
}

// ---------------- tensor product ----------------
template <int P, int L1, int L2, int L3, int MO>
__device__ __forceinline__ void tp_path(const float* __restrict__ wtp, int f,
                                        const float* __restrict__ Ms,
                                        const float (&vv)[3], const float (&yreg)[25],
                                        float (&acc)[25]) {
    float scale = wtp[P * NF + f] * vv[L1];
#pragma unroll
    for (int c = 0; c < 2 * L3 + 1; ++c) {
        float s = 0.f;
#pragma unroll
        for (int b = 0; b < 2 * L2 + 1; ++b)
            s += Ms[MO + b * (2 * L3 + 1) + c] * yreg[L2 * L2 + b];
        acc[L3 * L3 + c] += scale * s;
    }
}

__global__ __launch_bounds__(128) void tp_kernel(const float* __restrict__ wtp,
                                                 float* __restrict__ Out) {
    int e = blockIdx.x, f = threadIdx.x;
    __shared__ float Ms[703];
    __shared__ float shs[9];
    if (f < 9) shs[f] = g_shg[(size_t)e * 9 + f];
    __syncthreads();

    // build contracted M_p[b,c] = sum_a C[p][a][b][c] * sh[l1^2 + a]
    for (int idx = f; idx < 703; idx += 128) {
        int p = 0;
        while (dMOFF[p + 1] <= idx) ++p;
        int l1 = dPL1[p], l2 = dPL2[p], l3 = dPL3[p];
        (void)l2;
        int local = idx - dMOFF[p];
        int n3 = 2 * l3 + 1;
        int b = local / n3, c = local - b * n3;
        const float* Cp = g_C + p * 729 + b * 9 + c;
        float s = 0.f;
        for (int a = 0; a <= 2 * l1; ++a) s += Cp[a * 81] * shs[l1 * l1 + a];
        Ms[idx] = s;
    }
    __syncthreads();

    float yreg[25];
    size_t base = (size_t)e * (NM * NF) + f;
#pragma unroll
    for (int m = 0; m < NM; ++m) yreg[m] = g_y0[base + (size_t)m * NF];
    float vv[3];
#pragma unroll
    for (int l = 0; l < 3; ++l) vv[l] = g_v[((size_t)e * 3 + l) * NF + f];
    float acc[25];
#pragma unroll
    for (int m = 0; m < NM; ++m) acc[m] = 0.f;

    tp_path<0, 0, 0, 0, 0>(wtp, f, Ms, vv, yreg, acc);
    tp_path<1, 0, 1, 1, 1>(wtp, f, Ms, vv, yreg, acc);
    tp_path<2, 0, 2, 2, 10>(wtp, f, Ms, vv, yreg, acc);
    tp_path<3, 0, 3, 3, 35>(wtp, f, Ms, vv, yreg, acc);
    tp_path<4, 0, 4, 4, 84>(wtp, f, Ms, vv, yreg, acc);
    tp_path<5, 1, 0, 1, 165>(wtp, f, Ms, vv, yreg, acc);
    tp_path<6, 1, 1, 0, 168>(wtp, f, Ms, vv, yreg, acc);
    tp_path<7, 1, 1, 2, 171>(wtp, f, Ms, vv, yreg, acc);
    tp_path<8, 1, 2, 1, 186>(wtp, f, Ms, vv, yreg, acc);
    tp_path<9, 1, 2, 3, 201>(wtp, f, Ms, vv, yreg, acc);
    tp_path<10, 1, 3, 2, 236>(wtp, f, Ms, vv, yreg, acc);
    tp_path<11, 1, 3, 4, 271>(wtp, f, Ms, vv, yreg, acc);
    tp_path<12, 1, 4, 3, 334>(wtp, f, Ms, vv, yreg, acc);
    tp_path<13, 2, 0, 2, 397>(wtp, f, Ms, vv, yreg, acc);
    tp_path<14, 2, 1, 1, 402>(wtp, f, Ms, vv, yreg, acc);
    tp_path<15, 2, 1, 3, 411>(wtp, f, Ms, vv, yreg, acc);
    tp_path<16, 2, 2, 0, 432>(wtp, f, Ms, vv, yreg, acc);
    tp_path<17, 2, 2, 2, 437>(wtp, f, Ms, vv, yreg, acc);
    tp_path<18, 2, 2, 4, 462>(wtp, f, Ms, vv, yreg, acc);
    tp_path<19, 2, 3, 1, 507>(wtp, f, Ms, vv, yreg, acc);
    tp_path<20, 2, 3, 3, 528>(wtp, f, Ms, vv, yreg, acc);
    tp_path<21, 2, 4, 2, 577>(wtp, f, Ms, vv, yreg, acc);
    tp_path<22, 2, 4, 4, 622>(wtp, f, Ms, vv, yreg, acc);

#pragma unroll
    for (int m = 0; m < NM; ++m) Out[base + (size_t)m * NF] = acc[m];
}

// ---------------- launch ----------------
extern "C" void kernel_launch(void* const* d_in, const int* in_sizes, int n_in,
                              void* d_out, int out_size) {
    const float* desc = (const float*)d_in[0];
    const int*   nidx = (const int*)d_in[1];
    const float* disp = (const float*)d_in[2];
    const float* W1   = (const float*)d_in[3];
    const float* b1   = (const float*)d_in[4];
    const float* W2   = (const float*)d_in[5];
    const float* b2   = (const float*)d_in[6];
    const float* W3   = (const float*)d_in[7];
    const float* b3   = (const float*)d_in[8];
    const float* wtp  = (const float*)d_in[9];
    float* out = (float*)d_out;
    (void)in_sizes; (void)n_in; (void)out_size;

    cg_init_kernel<<<23, 128>>>();
    gather_kernel<<<N_E, 256>>>(desc, nidx);
    gemm25_kernel<0><<<dim3(N_E / 128, NM), 256>>>(W1, b1);
    norm_mish_kernel<<<N_E, 128>>>();
    gemm25_kernel<1><<<dim3(N_E / 128, NM), 256>>>(W2, b2);
    radsh_kernel<<<N_E, 128>>>(disp);
    gemmrad_kernel<<<dim3(N_E / 128, 3), 256>>>(W3, b3);
    tp_kernel<<<N_E, 128>>>(wtp, out);
}

// round 4
// speedup vs baseline: 1.0260x; 1.0260x over previous
#include <cuda_runtime.h>
#include <cuda_bf16.h>
#include <math.h>
#include <stdint.h>

#define N_E 16384
#define NF  128
#define NM  25

// ---------------- scratch (device globals; no allocation allowed) ----------------
__device__ float g_y0[(size_t)N_E * NM * NF];   // final y (post gemm2+res)
__device__ float g_y1[(size_t)N_E * NM * NF];   // post-W1 / post-mish
__device__ float g_rad[(size_t)N_E * NF];
__device__ float g_shg[(size_t)N_E * 9];
__device__ float g_v[(size_t)N_E * 3 * NF];
__device__ float g_C[23 * 729];                 // real CG tables [p][a][b][c] strides 81,9,1

__constant__ int dPL1[23]  = {0,0,0,0,0, 1,1,1,1,1,1,1,1, 2,2,2,2,2,2,2,2,2,2};
__constant__ int dPL2[23]  = {0,1,2,3,4, 0,1,1,2,2,3,3,4, 0,1,1,2,2,2,3,3,4,4};
__constant__ int dPL3[23]  = {0,1,2,3,4, 1,0,2,1,3,2,4,3, 2,1,3,0,2,4,1,3,2,4};
__constant__ int dMOFF[24] = {0,1,10,35,84,165,168,171,186,201,236,271,334,
                              397,402,411,432,437,462,507,528,577,622,703};

// ---------------- CG table computation (double, matches reference) ----------------
__device__ double factd(int n) { double r = 1.0; for (int i = 2; i <= n; ++i) r *= (double)i; return r; }

__device__ double cgc(int l1, int l2, int l3, int m1, int m2, int m3) {
    if (m1 + m2 != m3) return 0.0;
    if (l3 < abs(l1 - l2) || l3 > l1 + l2) return 0.0;
    double pre = sqrt((double)(2 * l3 + 1) * factd(l3 + l1 - l2) * factd(l3 - l1 + l2) *
                      factd(l1 + l2 - l3) / factd(l1 + l2 + l3 + 1));
    pre *= sqrt(factd(l3 + m3) * factd(l3 - m3) * factd(l1 - m1) * factd(l1 + m1) *
                factd(l2 - m2) * factd(l2 + m2));
    double s = 0.0;
    for (int k = 0; k <= l1 + l2 - l3; ++k) {
        int a0 = k, a1 = l1 + l2 - l3 - k, a2 = l1 - m1 - k, a3 = l2 + m2 - k;
        int a4 = l3 - l2 + m1 + k, a5 = l3 - l1 - m2 + k;
        if (a0 < 0 || a1 < 0 || a2 < 0 || a3 < 0 || a4 < 0 || a5 < 0) continue;
        double d = factd(a0) * factd(a1) * factd(a2) * factd(a3) * factd(a4) * factd(a5);
        s += ((k & 1) ? -1.0 : 1.0) / d;
    }
    return pre * s;
}

__device__ void u_elem(int l, int a, int A, double& re, double& im) {
    re = 0.0; im = 0.0;
    const double is2 = 0.70710678118654752440;
    int mA = A - l, ma = a - l;
    if (mA == 0) { if (ma == 0) re = 1.0; return; }
    int m = mA > 0 ? mA : -mA;
    double sgn = (m & 1) ? -1.0 : 1.0;
    if (mA > 0) {
        if (ma == m)       re = sgn * is2;
        else if (ma == -m) re = is2;
    } else {
        if (ma == m)       im = sgn * is2;
        else if (ma == -m) im = -is2;
    }
}

__global__ void cg_init_kernel() {
    int p = blockIdx.x;
    int l1 = dPL1[p], l2 = dPL2[p], l3 = dPL3[p];
    int n1 = 2 * l1 + 1, n2 = 2 * l2 + 1, n3 = 2 * l3 + 1;
    int total = n1 * n2 * n3;
    for (int idx = threadIdx.x; idx < total; idx += blockDim.x) {
        int A  = idx / (n2 * n3);
        int rm = idx % (n2 * n3);
        int B  = rm / n3;
        int Cc = rm % n3;
        double acc = 0.0;
        for (int a = 0; a < n1; ++a) {
            double u1r, u1i; u_elem(l1, a, A, u1r, u1i);
            if (u1r == 0.0 && u1i == 0.0) continue;
            int m1 = a - l1;
            for (int b = 0; b < n2; ++b) {
                double u2r, u2i; u_elem(l2, b, B, u2r, u2i);
                if (u2r == 0.0 && u2i == 0.0) continue;
                int m2 = b - l2;
                int m3 = m1 + m2;
                if (m3 < -l3 || m3 > l3) continue;
                double cg = cgc(l1, l2, l3, m1, m2, m3);
                if (cg == 0.0) continue;
                int c = l3 + m3;
                double u3r, u3i; u_elem(l3, c, Cc, u3r, u3i);
                double pr = u1r * u2r - u1i * u2i;
                double pi = u1r * u2i + u1i * u2r;
                acc += cg * (pr * u3r + pi * u3i);
            }
        }
        g_C[p * 729 + A * 81 + B * 9 + Cc] = (float)acc;
    }
}

// ================= mma.sync bf16 GEMM (hi/lo split, fp32 accumulate) =================
__device__ __forceinline__ uint32_t smem_u32(const void* p) {
    uint32_t a;
    asm("{ .reg .u64 t; cvta.to.shared.u64 t, %1; cvt.u32.u64 %0, t; }" : "=r"(a) : "l"(p));
    return a;
}

__device__ __forceinline__ void ldmA(uint32_t addr, uint32_t& a0, uint32_t& a1,
                                     uint32_t& a2, uint32_t& a3) {
    asm volatile("ldmatrix.sync.aligned.m8n8.x4.shared.b16 {%0,%1,%2,%3}, [%4];"
                 : "=r"(a0), "=r"(a1), "=r"(a2), "=r"(a3) : "r"(addr));
}
__device__ __forceinline__ void ldmB(uint32_t addr, uint32_t& b0, uint32_t& b1) {
    asm volatile("ldmatrix.sync.aligned.m8n8.x2.shared.b16 {%0,%1}, [%2];"
                 : "=r"(b0), "=r"(b1) : "r"(addr));
}
__device__ __forceinline__ void mma16816(float& c0, float& c1, float& c2, float& c3,
                                         uint32_t a0, uint32_t a1, uint32_t a2, uint32_t a3,
                                         uint32_t b0, uint32_t b1) {
    asm volatile("mma.sync.aligned.m16n8k16.row.col.f32.bf16.bf16.f32 "
                 "{%0,%1,%2,%3}, {%4,%5,%6,%7}, {%8,%9}, {%0,%1,%2,%3};"
                 : "+f"(c0), "+f"(c1), "+f"(c2), "+f"(c3)
                 : "r"(a0), "r"(a1), "r"(a2), "r"(a3), "r"(b0), "r"(b1));
}

// padded row-major bf16 tile: 128 rows x 128 cols, row stride 272 bytes (136 bf16)
#define ROWB 272
#define TILE_B (128 * ROWB)           // 34816 bytes per tile
#define TC_SMEM_BYTES (4 * TILE_B)    // A_hi, A_lo, B_hi, B_lo = 139264

// STAGE 0: X = desc[i]+desc[j] (gather fused), Y = g_y1, bias @ m==0
// STAGE 1: X = g_y1,  Y = g_y0 (+residual g_y1), bias @ m==0
// STAGE 2: X = g_rad, Y = g_v,  bias @ l==0
template <int STAGE>
__global__ __launch_bounds__(256, 1) void tc_gemm(const float* __restrict__ desc,
                                                  const int* __restrict__ nidx,
                                                  const float* __restrict__ Wall,
                                                  const float* __restrict__ bias) {
    extern __shared__ char smem[];
    char* sA_hi = smem;
    char* sA_lo = smem + TILE_B;
    char* sB_hi = smem + 2 * TILE_B;
    char* sB_lo = smem + 3 * TILE_B;
    float* Cs = reinterpret_cast<float*>(smem);   // reused after sync (128 x 132 floats)

    const int tid = threadIdx.x;
    const int wid = tid >> 5;
    const int lid = tid & 31;
    const int m = blockIdx.y;
    const int l = (STAGE == 2) ? m : ((m >= 16) ? 4 : (m >= 9) ? 3 : (m >= 4) ? 2 : (m >= 1) ? 1 : 0);
    const float* __restrict__ W = Wall + (size_t)l * NF * NF;
    const int e0 = blockIdx.x * 128;

    // ---- stage X into A_hi/A_lo ----
#pragma unroll
    for (int t = 0; t < 16; ++t) {
        int pos = t * 256 + tid;                // 4096 float4 slots
        int r = pos >> 5, k0 = (pos & 31) * 4;
        float4 x;
        if (STAGE == 0) {
            int e = e0 + r;
            int i = nidx[2 * e], j = nidx[2 * e + 1];
            float4 a = *reinterpret_cast<const float4*>(desc + ((size_t)i * NM + m) * NF + k0);
            float4 b = *reinterpret_cast<const float4*>(desc + ((size_t)j * NM + m) * NF + k0);
            x = make_float4(a.x + b.x, a.y + b.y, a.z + b.z, a.w + b.w);
        } else if (STAGE == 1) {
            x = *reinterpret_cast<const float4*>(g_y1 + ((size_t)(e0 + r) * NM + m) * NF + k0);
        } else {
            x = *reinterpret_cast<const float4*>(g_rad + (size_t)(e0 + r) * NF + k0);
        }
        __nv_bfloat162 h01 = __floats2bfloat162_rn(x.x, x.y);
        __nv_bfloat162 h23 = __floats2bfloat162_rn(x.z, x.w);
        __nv_bfloat162 l01 = __floats2bfloat162_rn(x.x - __bfloat162float(h01.x),
                                                   x.y - __bfloat162float(h01.y));
        __nv_bfloat162 l23 = __floats2bfloat162_rn(x.z - __bfloat162float(h23.x),
                                                   x.w - __bfloat162float(h23.y));
        uint32_t off = (uint32_t)r * ROWB + (uint32_t)k0 * 2;
        *reinterpret_cast<uint32_t*>(sA_hi + off)     = reinterpret_cast<uint32_t&>(h01);
        *reinterpret_cast<uint32_t*>(sA_hi + off + 4) = reinterpret_cast<uint32_t&>(h23);
        *reinterpret_cast<uint32_t*>(sA_lo + off)     = reinterpret_cast<uint32_t&>(l01);
        *reinterpret_cast<uint32_t*>(sA_lo + off + 4) = reinterpret_cast<uint32_t&>(l23);
    }

    // ---- stage W^T into B_hi/B_lo: Bt[n][k] = W[k][n] ----
#pragma unroll
    for (int t = 0; t < 16; ++t) {
        int pos = t * 256 + tid;
        int k = pos >> 5, n0 = (pos & 31) * 4;
        float4 w = *reinterpret_cast<const float4*>(W + (size_t)k * NF + n0);
        float wv[4] = {w.x, w.y, w.z, w.w};
#pragma unroll
        for (int q = 0; q < 4; ++q) {
            __nv_bfloat16 h  = __float2bfloat16_rn(wv[q]);
            __nv_bfloat16 lo = __float2bfloat16_rn(wv[q] - __bfloat162float(h));
            uint32_t off = (uint32_t)(n0 + q) * ROWB + (uint32_t)k * 2;
            *reinterpret_cast<unsigned short*>(sB_hi + off) = reinterpret_cast<unsigned short&>(h);
            *reinterpret_cast<unsigned short*>(sB_lo + off) = reinterpret_cast<unsigned short&>(lo);
        }
    }
    __syncthreads();

    // ---- 3 passes: Ahi*Bhi + Ahi*Blo + Alo*Bhi ----
    float acc[16][4];
#pragma unroll
    for (int nt = 0; nt < 16; ++nt)
#pragma unroll
        for (int q = 0; q < 4; ++q) acc[nt][q] = 0.f;

    const uint32_t aBaseHi = smem_u32(sA_hi);
    const uint32_t aBaseLo = smem_u32(sA_lo);
    const uint32_t bBaseHi = smem_u32(sB_hi);
    const uint32_t bBaseLo = smem_u32(sB_lo);
    const int arow = wid * 16 + (lid & 15);
    const int acolB = (lid >> 4) * 8;          // +0 or +8 (k offset in bf16)
    const int brow = lid & 7;
    const int bkoff = ((lid >> 3) & 1) * 8;

#pragma unroll
    for (int pass = 0; pass < 3; ++pass) {
        uint32_t aBase = (pass == 2) ? aBaseLo : aBaseHi;
        uint32_t bBase = (pass == 1) ? bBaseLo : bBaseHi;
#pragma unroll
        for (int k0 = 0; k0 < 128; k0 += 16) {
            uint32_t a0, a1, a2, a3;
            ldmA(aBase + (uint32_t)arow * ROWB + (uint32_t)(k0 + acolB) * 2, a0, a1, a2, a3);
#pragma unroll
            for (int nt = 0; nt < 16; ++nt) {
                uint32_t b0, b1;
                ldmB(bBase + (uint32_t)(nt * 8 + brow) * ROWB + (uint32_t)(k0 + bkoff) * 2, b0, b1);
                mma16816(acc[nt][0], acc[nt][1], acc[nt][2], acc[nt][3], a0, a1, a2, a3, b0, b1);
            }
        }
    }
    __syncthreads();   // done reading A/B; safe to reuse as Cs

    // ---- write fragments to Cs (row stride 132 floats) ----
    {
        int r0 = wid * 16 + (lid >> 2);
        int c0 = (lid & 3) * 2;
#pragma unroll
        for (int nt = 0; nt < 16; ++nt) {
            int c = nt * 8 + c0;
            *reinterpret_cast<float2*>(Cs + (size_t)r0 * 132 + c)       = make_float2(acc[nt][0], acc[nt][1]);
            *reinterpret_cast<float2*>(Cs + (size_t)(r0 + 8) * 132 + c) = make_float2(acc[nt][2], acc[nt][3]);
        }
    }
    __syncthreads();

    // ---- coalesced epilogue: bias, residual, store ----
    float* __restrict__ Y = (STAGE == 0) ? g_y1 : (STAGE == 1) ? g_y0 : g_v;
#pragma unroll
    for (int t = 0; t < 16; ++t) {
        int pos = t * 256 + tid;
        int r = pos >> 5, c4 = (pos & 31) * 4;
        float4 o = *reinterpret_cast<const float4*>(Cs + (size_t)r * 132 + c4);
        if (m == 0) {
            o.x += bias[c4]; o.y += bias[c4 + 1]; o.z += bias[c4 + 2]; o.w += bias[c4 + 3];
        }
        size_t obase = (STAGE == 2) ? (((size_t)(e0 + r) * 3 + m) * NF + c4)
                                    : (((size_t)(e0 + r) * NM + m) * NF + c4);
        if (STAGE == 1) {
            float4 rsd = *reinterpret_cast<const float4*>(g_y1 + obase);
            o.x += rsd.x; o.y += rsd.y; o.z += rsd.z; o.w += rsd.w;
        }
        *reinterpret_cast<float4*>(Y + obase) = o;
    }
}

// ---------------- normalize + gated mish (in place on g_y1) ----------------
__global__ __launch_bounds__(128) void norm_mish_kernel() {
    int e = blockIdx.x, f = threadIdx.x;
    size_t base = (size_t)e * (NM * NF) + f;
    float v[NM];
    float n2 = 0.f;
#pragma unroll
    for (int m = 0; m < NM; ++m) { v[m] = g_y1[base + (size_t)m * NF]; n2 += v[m] * v[m]; }
    float sc = rsqrtf(n2 + 1e-6f);
    float s = v[0] * sc;
    float sp = fmaxf(s, 0.f) + log1pf(expf(-fabsf(s)));
    float t = tanhf(sp);
    float sig = 1.f / (1.f + expf(-s));
    float dm = t + s * (1.f - t * t) * sig;
    g_y1[base] = s * t;
#pragma unroll
    for (int m = 1; m < NM; ++m) g_y1[base + (size_t)m * NF] = v[m] * sc * dm;
}

// ---------------- radial basis + spherical harmonics ----------------
__global__ __launch_bounds__(128) void radsh_kernel(const float* __restrict__ disp) {
    int e = blockIdx.x, f = threadIdx.x;
    float dx = disp[3 * e], dy = disp[3 * e + 1], dz = disp[3 * e + 2];
    float r = sqrtf(dx * dx + dy * dy + dz * dz + 1e-12f);
    float x = dx / r, y = dy / r, z = dz / r;
    float uc = r / 5.0f;
    float denom = fmaxf(1.f - uc * uc, 1e-9f);
    float cut = (uc < 1.f) ? expf(1.f - 1.f / denom) : 0.f;
    float ang = 3.14159265358979323846f * r / 5.0f;
    g_rad[(size_t)e * NF + f] = cosf((float)f * ang) * cut;
    if (f < 9) {
        const float s3 = 1.7320508075688772f;
        float shv;
        switch (f) {
            case 0: shv = 1.f; break;
            case 1: shv = y; break;
            case 2: shv = z; break;
            case 3: shv = x; break;
            case 4: shv = s3 * x * y; break;
            case 5: shv = s3 * y * z; break;
            case 6: shv = 0.5f * (3.f * z * z - 1.f); break;
            case 7: shv = s3 * x * z; break;
            default: shv = 0.5f * s3 * (x * x - y * y); break;
        }
        g_shg[(size_t)e * 9 + f] = shv;
    }
}

// ---------------- tensor product ----------------
template <int P, int L1, int L2, int L3, int MO>
__device__ __forceinline__ void tp_path(const float* __restrict__ wtp, int f,
                                        const float* __restrict__ Ms,
                                        const float (&vv)[3], const float (&yreg)[25],
                                        float (&acc)[25]) {
    float scale = wtp[P * NF + f] * vv[L1];
#pragma unroll
    for (int c = 0; c < 2 * L3 + 1; ++c) {
        float s = 0.f;
#pragma unroll
        for (int b = 0; b < 2 * L2 + 1; ++b)
            s += Ms[MO + b * (2 * L3 + 1) + c] * yreg[L2 * L2 + b];
        acc[L3 * L3 + c] += scale * s;
    }
}

__global__ __launch_bounds__(128) void tp_kernel(const float* __restrict__ wtp,
                                                 float* __restrict__ Out) {
    int e = blockIdx.x, f = threadIdx.x;
    __shared__ float Ms[703];
    __shared__ float shs[9];
    if (f < 9) shs[f] = g_shg[(size_t)e * 9 + f];
    __syncthreads();

    for (int idx = f; idx < 703; idx += 128) {
        int p = 0;
        while (dMOFF[p + 1] <= idx) ++p;
        int l1 = dPL1[p], l3 = dPL3[p];
        int local = idx - dMOFF[p];
        int n3 = 2 * l3 + 1;
        int b = local / n3, c = local - b * n3;
        const float* Cp = g_C + p * 729 + b * 9 + c;
        float s = 0.f;
        for (int a = 0; a <= 2 * l1; ++a) s += Cp[a * 81] * shs[l1 * l1 + a];
        Ms[idx] = s;
    }
    __syncthreads();

    float yreg[25];
    size_t base = (size_t)e * (NM * NF) + f;
#pragma unroll
    for (int m = 0; m < NM; ++m) yreg[m] = g_y0[base + (size_t)m * NF];
    float vv[3];
#pragma unroll
    for (int l = 0; l < 3; ++l) vv[l] = g_v[((size_t)e * 3 + l) * NF + f];
    float acc[25];
#pragma unroll
    for (int m = 0; m < NM; ++m) acc[m] = 0.f;

    tp_path<0, 0, 0, 0, 0>(wtp, f, Ms, vv, yreg, acc);
    tp_path<1, 0, 1, 1, 1>(wtp, f, Ms, vv, yreg, acc);
    tp_path<2, 0, 2, 2, 10>(wtp, f, Ms, vv, yreg, acc);
    tp_path<3, 0, 3, 3, 35>(wtp, f, Ms, vv, yreg, acc);
    tp_path<4, 0, 4, 4, 84>(wtp, f, Ms, vv, yreg, acc);
    tp_path<5, 1, 0, 1, 165>(wtp, f, Ms, vv, yreg, acc);
    tp_path<6, 1, 1, 0, 168>(wtp, f, Ms, vv, yreg, acc);
    tp_path<7, 1, 1, 2, 171>(wtp, f, Ms, vv, yreg, acc);
    tp_path<8, 1, 2, 1, 186>(wtp, f, Ms, vv, yreg, acc);
    tp_path<9, 1, 2, 3, 201>(wtp, f, Ms, vv, yreg, acc);
    tp_path<10, 1, 3, 2, 236>(wtp, f, Ms, vv, yreg, acc);
    tp_path<11, 1, 3, 4, 271>(wtp, f, Ms, vv, yreg, acc);
    tp_path<12, 1, 4, 3, 334>(wtp, f, Ms, vv, yreg, acc);
    tp_path<13, 2, 0, 2, 397>(wtp, f, Ms, vv, yreg, acc);
    tp_path<14, 2, 1, 1, 402>(wtp, f, Ms, vv, yreg, acc);
    tp_path<15, 2, 1, 3, 411>(wtp, f, Ms, vv, yreg, acc);
    tp_path<16, 2, 2, 0, 432>(wtp, f, Ms, vv, yreg, acc);
    tp_path<17, 2, 2, 2, 437>(wtp, f, Ms, vv, yreg, acc);
    tp_path<18, 2, 2, 4, 462>(wtp, f, Ms, vv, yreg, acc);
    tp_path<19, 2, 3, 1, 507>(wtp, f, Ms, vv, yreg, acc);
    tp_path<20, 2, 3, 3, 528>(wtp, f, Ms, vv, yreg, acc);
    tp_path<21, 2, 4, 2, 577>(wtp, f, Ms, vv, yreg, acc);
    tp_path<22, 2, 4, 4, 622>(wtp, f, Ms, vv, yreg, acc);

#pragma unroll
    for (int m = 0; m < NM; ++m) Out[base + (size_t)m * NF] = acc[m];
}

// ---------------- launch ----------------
extern "C" void kernel_launch(void* const* d_in, const int* in_sizes, int n_in,
                              void* d_out, int out_size) {
    const float* desc = (const float*)d_in[0];
    const int*   nidx = (const int*)d_in[1];
    const float* disp = (const float*)d_in[2];
    const float* W1   = (const float*)d_in[3];
    const float* b1   = (const float*)d_in[4];
    const float* W2   = (const float*)d_in[5];
    const float* b2   = (const float*)d_in[6];
    const float* W3   = (const float*)d_in[7];
    const float* b3   = (const float*)d_in[8];
    const float* wtp  = (const float*)d_in[9];
    float* out = (float*)d_out;
    (void)in_sizes; (void)n_in; (void)out_size;

    static int attr_set = 0;
    if (!attr_set) {
        cudaFuncSetAttribute(tc_gemm<0>, cudaFuncAttributeMaxDynamicSharedMemorySize, TC_SMEM_BYTES);
        cudaFuncSetAttribute(tc_gemm<1>, cudaFuncAttributeMaxDynamicSharedMemorySize, TC_SMEM_BYTES);
        cudaFuncSetAttribute(tc_gemm<2>, cudaFuncAttributeMaxDynamicSharedMemorySize, TC_SMEM_BYTES);
        attr_set = 1;
    }

    cg_init_kernel<<<23, 128>>>();
    tc_gemm<0><<<dim3(N_E / 128, NM), 256, TC_SMEM_BYTES>>>(desc, nidx, W1, b1);
    norm_mish_kernel<<<N_E, 128>>>();
    tc_gemm<1><<<dim3(N_E / 128, NM), 256, TC_SMEM_BYTES>>>(desc, nidx, W2, b2);
    radsh_kernel<<<N_E, 128>>>(disp);
    tc_gemm<2><<<dim3(N_E / 128, 3), 256, TC_SMEM_BYTES>>>(desc, nidx, W3, b3);
    tp_kernel<<<N_E, 128>>>(wtp, out);
}

// round 5
// speedup vs baseline: 1.1090x; 1.0809x over previous
#include <cuda_runtime.h>
#include <cuda_bf16.h>
#include <math.h>
#include <stdint.h>

#define N_E 16384
#define NF  128
#define NM  25

// ---------------- scratch (device globals; no allocation allowed) ----------------
__device__ float g_y0[(size_t)N_E * NM * NF];   // final y (post gemm2+res)
__device__ float g_y1[(size_t)N_E * NM * NF];   // post-W1 / post-mish
__device__ float g_rad[(size_t)N_E * NF];
__device__ float g_shg[(size_t)N_E * 9];
__device__ float g_v[(size_t)N_E * 3 * NF];
__device__ float g_C[23 * 729];                 // real CG tables [p][a][b][c] strides 81,9,1

__constant__ int dPL1[23]  = {0,0,0,0,0, 1,1,1,1,1,1,1,1, 2,2,2,2,2,2,2,2,2,2};
__constant__ int dPL2[23]  = {0,1,2,3,4, 0,1,1,2,2,3,3,4, 0,1,1,2,2,2,3,3,4,4};
__constant__ int dPL3[23]  = {0,1,2,3,4, 1,0,2,1,3,2,4,3, 2,1,3,0,2,4,1,3,2,4};
__constant__ int dMOFF[24] = {0,1,10,35,84,165,168,171,186,201,236,271,334,
                              397,402,411,432,437,462,507,528,577,622,703};

// ---------------- CG table computation (double, matches reference) ----------------
__device__ double factd(int n) { double r = 1.0; for (int i = 2; i <= n; ++i) r *= (double)i; return r; }

__device__ double cgc(int l1, int l2, int l3, int m1, int m2, int m3) {
    if (m1 + m2 != m3) return 0.0;
    if (l3 < abs(l1 - l2) || l3 > l1 + l2) return 0.0;
    double pre = sqrt((double)(2 * l3 + 1) * factd(l3 + l1 - l2) * factd(l3 - l1 + l2) *
                      factd(l1 + l2 - l3) / factd(l1 + l2 + l3 + 1));
    pre *= sqrt(factd(l3 + m3) * factd(l3 - m3) * factd(l1 - m1) * factd(l1 + m1) *
                factd(l2 - m2) * factd(l2 + m2));
    double s = 0.0;
    for (int k = 0; k <= l1 + l2 - l3; ++k) {
        int a0 = k, a1 = l1 + l2 - l3 - k, a2 = l1 - m1 - k, a3 = l2 + m2 - k;
        int a4 = l3 - l2 + m1 + k, a5 = l3 - l1 - m2 + k;
        if (a0 < 0 || a1 < 0 || a2 < 0 || a3 < 0 || a4 < 0 || a5 < 0) continue;
        double d = factd(a0) * factd(a1) * factd(a2) * factd(a3) * factd(a4) * factd(a5);
        s += ((k & 1) ? -1.0 : 1.0) / d;
    }
    return pre * s;
}

__device__ void u_elem(int l, int a, int A, double& re, double& im) {
    re = 0.0; im = 0.0;
    const double is2 = 0.70710678118654752440;
    int mA = A - l, ma = a - l;
    if (mA == 0) { if (ma == 0) re = 1.0; return; }
    int m = mA > 0 ? mA : -mA;
    double sgn = (m & 1) ? -1.0 : 1.0;
    if (mA > 0) {
        if (ma == m)       re = sgn * is2;
        else if (ma == -m) re = is2;
    } else {
        if (ma == m)       im = sgn * is2;
        else if (ma == -m) im = -is2;
    }
}

__global__ void cg_init_kernel() {
    int p = blockIdx.x;
    int l1 = dPL1[p], l2 = dPL2[p], l3 = dPL3[p];
    int n1 = 2 * l1 + 1, n2 = 2 * l2 + 1, n3 = 2 * l3 + 1;
    int total = n1 * n2 * n3;
    for (int idx = threadIdx.x; idx < total; idx += blockDim.x) {
        int A  = idx / (n2 * n3);
        int rm = idx % (n2 * n3);
        int B  = rm / n3;
        int Cc = rm % n3;
        double acc = 0.0;
        for (int a = 0; a < n1; ++a) {
            double u1r, u1i; u_elem(l1, a, A, u1r, u1i);
            if (u1r == 0.0 && u1i == 0.0) continue;
            int m1 = a - l1;
            for (int b = 0; b < n2; ++b) {
                double u2r, u2i; u_elem(l2, b, B, u2r, u2i);
                if (u2r == 0.0 && u2i == 0.0) continue;
                int m2 = b - l2;
                int m3 = m1 + m2;
                if (m3 < -l3 || m3 > l3) continue;
                double cg = cgc(l1, l2, l3, m1, m2, m3);
                if (cg == 0.0) continue;
                int c = l3 + m3;
                double u3r, u3i; u_elem(l3, c, Cc, u3r, u3i);
                double pr = u1r * u2r - u1i * u2i;
                double pi = u1r * u2i + u1i * u2r;
                acc += cg * (pr * u3r + pi * u3i);
            }
        }
        g_C[p * 729 + A * 81 + B * 9 + Cc] = (float)acc;
    }
}

// ================= mma.sync bf16 GEMM (hi/lo split, fp32 accumulate) =================
__device__ __forceinline__ uint32_t smem_u32(const void* p) {
    uint32_t a;
    asm("{ .reg .u64 t; cvta.to.shared.u64 t, %1; cvt.u32.u64 %0, t; }" : "=r"(a) : "l"(p));
    return a;
}

__device__ __forceinline__ void ldm4(uint32_t addr, uint32_t& a0, uint32_t& a1,
                                     uint32_t& a2, uint32_t& a3) {
    asm volatile("ldmatrix.sync.aligned.m8n8.x4.shared.b16 {%0,%1,%2,%3}, [%4];"
                 : "=r"(a0), "=r"(a1), "=r"(a2), "=r"(a3) : "r"(addr));
}
__device__ __forceinline__ void mma16816(float* c,
                                         uint32_t a0, uint32_t a1, uint32_t a2, uint32_t a3,
                                         uint32_t b0, uint32_t b1) {
    asm volatile("mma.sync.aligned.m16n8k16.row.col.f32.bf16.bf16.f32 "
                 "{%0,%1,%2,%3}, {%4,%5,%6,%7}, {%8,%9}, {%0,%1,%2,%3};"
                 : "+f"(c[0]), "+f"(c[1]), "+f"(c[2]), "+f"(c[3])
                 : "r"(a0), "r"(a1), "r"(a2), "r"(a3), "r"(b0), "r"(b1));
}

// padded row-major bf16 tile: 128 rows x 128 cols, row stride 272 bytes (136 bf16)
#define ROWB 272
#define TILE_B (128 * ROWB)           // 34816 bytes per tile
#define TC_SMEM_BYTES (4 * TILE_B)    // A_hi, A_lo, B_hi, B_lo = 139264

// STAGE 0: X = desc[i]+desc[j] (gather fused), Y = g_y1, bias @ m==0
// STAGE 1: X = g_y1,  Y = g_y0 (+residual g_y1), bias @ m==0
// STAGE 2: X = g_rad, Y = g_v,  bias @ l==0
template <int STAGE>
__global__ __launch_bounds__(256, 1) void tc_gemm(const float* __restrict__ desc,
                                                  const int* __restrict__ nidx,
                                                  const float* __restrict__ Wall,
                                                  const float* __restrict__ bias) {
    extern __shared__ char smem[];
    char* sA_hi = smem;
    char* sA_lo = smem + TILE_B;
    char* sB_hi = smem + 2 * TILE_B;
    char* sB_lo = smem + 3 * TILE_B;
    float* Cs = reinterpret_cast<float*>(smem);   // reused after sync (128 x 132 floats)

    const int tid = threadIdx.x;
    const int wid = tid >> 5;
    const int lid = tid & 31;
    const int m = blockIdx.y;
    const int l = (STAGE == 2) ? m : ((m >= 16) ? 4 : (m >= 9) ? 3 : (m >= 4) ? 2 : (m >= 1) ? 1 : 0);
    const float* __restrict__ W = Wall + (size_t)l * NF * NF;
    const int e0 = blockIdx.x * 128;

    // ---- stage X into A_hi/A_lo ----
#pragma unroll
    for (int t = 0; t < 16; ++t) {
        int pos = t * 256 + tid;                // 4096 float4 slots
        int r = pos >> 5, k0 = (pos & 31) * 4;
        float4 x;
        if (STAGE == 0) {
            int e = e0 + r;
            int i = nidx[2 * e], j = nidx[2 * e + 1];
            float4 a = *reinterpret_cast<const float4*>(desc + ((size_t)i * NM + m) * NF + k0);
            float4 b = *reinterpret_cast<const float4*>(desc + ((size_t)j * NM + m) * NF + k0);
            x = make_float4(a.x + b.x, a.y + b.y, a.z + b.z, a.w + b.w);
        } else if (STAGE == 1) {
            x = *reinterpret_cast<const float4*>(g_y1 + ((size_t)(e0 + r) * NM + m) * NF + k0);
        } else {
            x = *reinterpret_cast<const float4*>(g_rad + (size_t)(e0 + r) * NF + k0);
        }
        __nv_bfloat162 h01 = __floats2bfloat162_rn(x.x, x.y);
        __nv_bfloat162 h23 = __floats2bfloat162_rn(x.z, x.w);
        __nv_bfloat162 l01 = __floats2bfloat162_rn(x.x - __bfloat162float(h01.x),
                                                   x.y - __bfloat162float(h01.y));
        __nv_bfloat162 l23 = __floats2bfloat162_rn(x.z - __bfloat162float(h23.x),
                                                   x.w - __bfloat162float(h23.y));
        uint32_t off = (uint32_t)r * ROWB + (uint32_t)k0 * 2;
        *reinterpret_cast<uint32_t*>(sA_hi + off)     = reinterpret_cast<uint32_t&>(h01);
        *reinterpret_cast<uint32_t*>(sA_hi + off + 4) = reinterpret_cast<uint32_t&>(h23);
        *reinterpret_cast<uint32_t*>(sA_lo + off)     = reinterpret_cast<uint32_t&>(l01);
        *reinterpret_cast<uint32_t*>(sA_lo + off + 4) = reinterpret_cast<uint32_t&>(l23);
    }

    // ---- stage W^T into B_hi/B_lo: Bt[n][k] = W[k][n] ----
#pragma unroll
    for (int t = 0; t < 16; ++t) {
        int pos = t * 256 + tid;
        int k = pos >> 5, n0 = (pos & 31) * 4;
        float4 w = *reinterpret_cast<const float4*>(W + (size_t)k * NF + n0);
        float wv[4] = {w.x, w.y, w.z, w.w};
#pragma unroll
        for (int q = 0; q < 4; ++q) {
            __nv_bfloat16 h  = __float2bfloat16_rn(wv[q]);
            __nv_bfloat16 lo = __float2bfloat16_rn(wv[q] - __bfloat162float(h));
            uint32_t off = (uint32_t)(n0 + q) * ROWB + (uint32_t)k * 2;
            *reinterpret_cast<unsigned short*>(sB_hi + off) = reinterpret_cast<unsigned short&>(h);
            *reinterpret_cast<unsigned short*>(sB_lo + off) = reinterpret_cast<unsigned short&>(lo);
        }
    }
    __syncthreads();

    // ---- fused 3-product mainloop: each fragment loaded ONCE per k-step ----
    // warps: 4x2 grid; warp tile = 32 rows x 64 cols
    const int wr = wid >> 1;            // 0..3
    const int wc = wid & 1;             // 0..1
    const int r0 = wr * 32;
    const int c0 = wc * 64;

    const uint32_t aBaseHi = smem_u32(sA_hi);
    const uint32_t aBaseLo = smem_u32(sA_lo);
    const uint32_t bBaseHi = smem_u32(sB_hi);
    const uint32_t bBaseLo = smem_u32(sB_lo);

    // A x4 addressing (16x16 tile): lanes 0-15 -> rows, lane>>4 -> k half
    const int a_r = lid & 15;
    const int a_k = (lid >> 4) * 8;
    // B x4 addressing (16 cols x 16 k): lane group g=lid>>3: n_off=(g>>1)*8, k_off=(g&1)*8
    const int b_n = ((lid >> 4) & 1) * 8 + (lid & 7);
    const int b_k = ((lid >> 3) & 1) * 8;

    float acc[16][4];
#pragma unroll
    for (int t = 0; t < 16; ++t)
#pragma unroll
        for (int q = 0; q < 4; ++q) acc[t][q] = 0.f;

#pragma unroll
    for (int k0 = 0; k0 < 128; k0 += 16) {
        uint32_t ah[2][4], al[2][4], bh[4][4], bl[4][4];
#pragma unroll
        for (int rt = 0; rt < 2; ++rt) {
            uint32_t aoff = (uint32_t)(r0 + rt * 16 + a_r) * ROWB + (uint32_t)(k0 + a_k) * 2;
            ldm4(aBaseHi + aoff, ah[rt][0], ah[rt][1], ah[rt][2], ah[rt][3]);
            ldm4(aBaseLo + aoff, al[rt][0], al[rt][1], al[rt][2], al[rt][3]);
        }
#pragma unroll
        for (int bt = 0; bt < 4; ++bt) {
            uint32_t boff = (uint32_t)(c0 + bt * 16 + b_n) * ROWB + (uint32_t)(k0 + b_k) * 2;
            ldm4(bBaseHi + boff, bh[bt][0], bh[bt][1], bh[bt][2], bh[bt][3]);
            ldm4(bBaseLo + boff, bl[bt][0], bl[bt][1], bl[bt][2], bl[bt][3]);
        }
#pragma unroll
        for (int rt = 0; rt < 2; ++rt) {
#pragma unroll
            for (int bt = 0; bt < 4; ++bt) {
                float* c0p = acc[rt * 8 + bt * 2];
                float* c1p = acc[rt * 8 + bt * 2 + 1];
                mma16816(c0p, ah[rt][0], ah[rt][1], ah[rt][2], ah[rt][3], bh[bt][0], bh[bt][1]);
                mma16816(c1p, ah[rt][0], ah[rt][1], ah[rt][2], ah[rt][3], bh[bt][2], bh[bt][3]);
                mma16816(c0p, ah[rt][0], ah[rt][1], ah[rt][2], ah[rt][3], bl[bt][0], bl[bt][1]);
                mma16816(c1p, ah[rt][0], ah[rt][1], ah[rt][2], ah[rt][3], bl[bt][2], bl[bt][3]);
                mma16816(c0p, al[rt][0], al[rt][1], al[rt][2], al[rt][3], bh[bt][0], bh[bt][1]);
                mma16816(c1p, al[rt][0], al[rt][1], al[rt][2], al[rt][3], bh[bt][2], bh[bt][3]);
            }
        }
    }
    __syncthreads();   // done reading A/B; safe to reuse as Cs

    // ---- write fragments to Cs (row stride 132 floats) ----
#pragma unroll
    for (int rt = 0; rt < 2; ++rt) {
#pragma unroll
        for (int nt = 0; nt < 8; ++nt) {
            float* a = acc[rt * 8 + nt];
            int rr = r0 + rt * 16 + (lid >> 2);
            int cc = c0 + nt * 8 + (lid & 3) * 2;
            *reinterpret_cast<float2*>(Cs + (size_t)rr * 132 + cc)       = make_float2(a[0], a[1]);
            *reinterpret_cast<float2*>(Cs + (size_t)(rr + 8) * 132 + cc) = make_float2(a[2], a[3]);
        }
    }
    __syncthreads();

    // ---- coalesced epilogue: bias, residual, store ----
    float* __restrict__ Y = (STAGE == 0) ? g_y1 : (STAGE == 1) ? g_y0 : g_v;
#pragma unroll
    for (int t = 0; t < 16; ++t) {
        int pos = t * 256 + tid;
        int r = pos >> 5, c4 = (pos & 31) * 4;
        float4 o = *reinterpret_cast<const float4*>(Cs + (size_t)r * 132 + c4);
        if (m == 0) {
            o.x += bias[c4]; o.y += bias[c4 + 1]; o.z += bias[c4 + 2]; o.w += bias[c4 + 3];
        }
        size_t obase = (STAGE == 2) ? (((size_t)(e0 + r) * 3 + m) * NF + c4)
                                    : (((size_t)(e0 + r) * NM + m) * NF + c4);
        if (STAGE == 1) {
            float4 rsd = *reinterpret_cast<const float4*>(g_y1 + obase);
            o.x += rsd.x; o.y += rsd.y; o.z += rsd.z; o.w += rsd.w;
        }
        *reinterpret_cast<float4*>(Y + obase) = o;
    }
}

// ---------------- normalize + gated mish (in place on g_y1) ----------------
__global__ __launch_bounds__(128) void norm_mish_kernel() {
    int e = blockIdx.x, f = threadIdx.x;
    size_t base = (size_t)e * (NM * NF) + f;
    float v[NM];
    float n2 = 0.f;
#pragma unroll
    for (int m = 0; m < NM; ++m) { v[m] = g_y1[base + (size_t)m * NF]; n2 += v[m] * v[m]; }
    float sc = rsqrtf(n2 + 1e-6f);
    float s = v[0] * sc;
    float sp = fmaxf(s, 0.f) + log1pf(expf(-fabsf(s)));
    float t = tanhf(sp);
    float sig = 1.f / (1.f + expf(-s));
    float dm = t + s * (1.f - t * t) * sig;
    g_y1[base] = s * t;
#pragma unroll
    for (int m = 1; m < NM; ++m) g_y1[base + (size_t)m * NF] = v[m] * sc * dm;
}

// ---------------- radial basis + spherical harmonics ----------------
__global__ __launch_bounds__(128) void radsh_kernel(const float* __restrict__ disp) {
    int e = blockIdx.x, f = threadIdx.x;
    float dx = disp[3 * e], dy = disp[3 * e + 1], dz = disp[3 * e + 2];
    float r = sqrtf(dx * dx + dy * dy + dz * dz + 1e-12f);
    float x = dx / r, y = dy / r, z = dz / r;
    float uc = r / 5.0f;
    float denom = fmaxf(1.f - uc * uc, 1e-9f);
    float cut = (uc < 1.f) ? expf(1.f - 1.f / denom) : 0.f;
    float ang = 3.14159265358979323846f * r / 5.0f;
    g_rad[(size_t)e * NF + f] = cosf((float)f * ang) * cut;
    if (f < 9) {
        const float s3 = 1.7320508075688772f;
        float shv;
        switch (f) {
            case 0: shv = 1.f; break;
            case 1: shv = y; break;
            case 2: shv = z; break;
            case 3: shv = x; break;
            case 4: shv = s3 * x * y; break;
            case 5: shv = s3 * y * z; break;
            case 6: shv = 0.5f * (3.f * z * z - 1.f); break;
            case 7: shv = s3 * x * z; break;
            default: shv = 0.5f * s3 * (x * x - y * y); break;
        }
        g_shg[(size_t)e * 9 + f] = shv;
    }
}

// ---------------- tensor product ----------------
template <int P, int L1, int L2, int L3, int MO>
__device__ __forceinline__ void tp_path(const float* __restrict__ wtp, int f,
                                        const float* __restrict__ Ms,
                                        const float (&vv)[3], const float (&yreg)[25],
                                        float (&acc)[25]) {
    float scale = wtp[P * NF + f] * vv[L1];
#pragma unroll
    for (int c = 0; c < 2 * L3 + 1; ++c) {
        float s = 0.f;
#pragma unroll
        for (int b = 0; b < 2 * L2 + 1; ++b)
            s += Ms[MO + b * (2 * L3 + 1) + c] * yreg[L2 * L2 + b];
        acc[L3 * L3 + c] += scale * s;
    }
}

__global__ __launch_bounds__(128) void tp_kernel(const float* __restrict__ wtp,
                                                 float* __restrict__ Out) {
    int e = blockIdx.x, f = threadIdx.x;
    __shared__ float Ms[703];
    __shared__ float shs[9];
    if (f < 9) shs[f] = g_shg[(size_t)e * 9 + f];
    __syncthreads();

    for (int idx = f; idx < 703; idx += 128) {
        int p = 0;
        while (dMOFF[p + 1] <= idx) ++p;
        int l1 = dPL1[p], l3 = dPL3[p];
        int local = idx - dMOFF[p];
        int n3 = 2 * l3 + 1;
        int b = local / n3, c = local - b * n3;
        const float* Cp = g_C + p * 729 + b * 9 + c;
        float s = 0.f;
        for (int a = 0; a <= 2 * l1; ++a) s += Cp[a * 81] * shs[l1 * l1 + a];
        Ms[idx] = s;
    }
    __syncthreads();

    float yreg[25];
    size_t base = (size_t)e * (NM * NF) + f;
#pragma unroll
    for (int m = 0; m < NM; ++m) yreg[m] = g_y0[base + (size_t)m * NF];
    float vv[3];
#pragma unroll
    for (int l = 0; l < 3; ++l) vv[l] = g_v[((size_t)e * 3 + l) * NF + f];
    float acc[25];
#pragma unroll
    for (int m = 0; m < NM; ++m) acc[m] = 0.f;

    tp_path<0, 0, 0, 0, 0>(wtp, f, Ms, vv, yreg, acc);
    tp_path<1, 0, 1, 1, 1>(wtp, f, Ms, vv, yreg, acc);
    tp_path<2, 0, 2, 2, 10>(wtp, f, Ms, vv, yreg, acc);
    tp_path<3, 0, 3, 3, 35>(wtp, f, Ms, vv, yreg, acc);
    tp_path<4, 0, 4, 4, 84>(wtp, f, Ms, vv, yreg, acc);
    tp_path<5, 1, 0, 1, 165>(wtp, f, Ms, vv, yreg, acc);
    tp_path<6, 1, 1, 0, 168>(wtp, f, Ms, vv, yreg, acc);
    tp_path<7, 1, 1, 2, 171>(wtp, f, Ms, vv, yreg, acc);
    tp_path<8, 1, 2, 1, 186>(wtp, f, Ms, vv, yreg, acc);
    tp_path<9, 1, 2, 3, 201>(wtp, f, Ms, vv, yreg, acc);
    tp_path<10, 1, 3, 2, 236>(wtp, f, Ms, vv, yreg, acc);
    tp_path<11, 1, 3, 4, 271>(wtp, f, Ms, vv, yreg, acc);
    tp_path<12, 1, 4, 3, 334>(wtp, f, Ms, vv, yreg, acc);
    tp_path<13, 2, 0, 2, 397>(wtp, f, Ms, vv, yreg, acc);
    tp_path<14, 2, 1, 1, 402>(wtp, f, Ms, vv, yreg, acc);
    tp_path<15, 2, 1, 3, 411>(wtp, f, Ms, vv, yreg, acc);
    tp_path<16, 2, 2, 0, 432>(wtp, f, Ms, vv, yreg, acc);
    tp_path<17, 2, 2, 2, 437>(wtp, f, Ms, vv, yreg, acc);
    tp_path<18, 2, 2, 4, 462>(wtp, f, Ms, vv, yreg, acc);
    tp_path<19, 2, 3, 1, 507>(wtp, f, Ms, vv, yreg, acc);
    tp_path<20, 2, 3, 3, 528>(wtp, f, Ms, vv, yreg, acc);
    tp_path<21, 2, 4, 2, 577>(wtp, f, Ms, vv, yreg, acc);
    tp_path<22, 2, 4, 4, 622>(wtp, f, Ms, vv, yreg, acc);

#pragma unroll
    for (int m = 0; m < NM; ++m) Out[base + (size_t)m * NF] = acc[m];
}

// ---------------- launch ----------------
extern "C" void kernel_launch(void* const* d_in, const int* in_sizes, int n_in,
                              void* d_out, int out_size) {
    const float* desc = (const float*)d_in[0];
    const int*   nidx = (const int*)d_in[1];
    const float* disp = (const float*)d_in[2];
    const float* W1   = (const float*)d_in[3];
    const float* b1   = (const float*)d_in[4];
    const float* W2   = (const float*)d_in[5];
    const float* b2   = (const float*)d_in[6];
    const float* W3   = (const float*)d_in[7];
    const float* b3   = (const float*)d_in[8];
    const float* wtp  = (const float*)d_in[9];
    float* out = (float*)d_out;
    (void)in_sizes; (void)n_in; (void)out_size;

    static int attr_set = 0;
    if (!attr_set) {
        cudaFuncSetAttribute(tc_gemm<0>, cudaFuncAttributeMaxDynamicSharedMemorySize, TC_SMEM_BYTES);
        cudaFuncSetAttribute(tc_gemm<1>, cudaFuncAttributeMaxDynamicSharedMemorySize, TC_SMEM_BYTES);
        cudaFuncSetAttribute(tc_gemm<2>, cudaFuncAttributeMaxDynamicSharedMemorySize, TC_SMEM_BYTES);
        attr_set = 1;
    }

    cg_init_kernel<<<23, 128>>>();
    tc_gemm<0><<<dim3(N_E / 128, NM), 256, TC_SMEM_BYTES>>>(desc, nidx, W1, b1);
    norm_mish_kernel<<<N_E, 128>>>();
    tc_gemm<1><<<dim3(N_E / 128, NM), 256, TC_SMEM_BYTES>>>(desc, nidx, W2, b2);
    radsh_kernel<<<N_E, 128>>>(disp);
    tc_gemm<2><<<dim3(N_E / 128, 3), 256, TC_SMEM_BYTES>>>(desc, nidx, W3, b3);
    tp_kernel<<<N_E, 128>>>(wtp, out);
}

// round 6
// speedup vs baseline: 1.6087x; 1.4506x over previous
#include <cuda_runtime.h>
#include <cuda_bf16.h>
#include <math.h>
#include <stdint.h>

#define N_E 16384
#define NF  128
#define NM  25

// ---------------- scratch (device globals; no allocation allowed) ----------------
__device__ float g_y0[(size_t)N_E * NM * NF];   // final y (post gemm2+res)
__device__ float g_y1[(size_t)N_E * NM * NF];   // post-W1 / post-mish
__device__ float g_rad[(size_t)N_E * NF];
__device__ float g_shg[(size_t)N_E * 9];
__device__ float g_v[(size_t)N_E * 3 * NF];
__device__ float g_C[23 * 729];                 // real CG tables [p][a][b][c] strides 81,9,1
// precomputed B register fragments: [13 mats][2 wc][8 kstep][4 bt][32 lane]
__device__ uint4 g_BfH[13 * 2 * 8 * 4 * 32];
__device__ uint4 g_BfL[13 * 2 * 8 * 4 * 32];

__constant__ int dPL1[23]  = {0,0,0,0,0, 1,1,1,1,1,1,1,1, 2,2,2,2,2,2,2,2,2,2};
__constant__ int dPL2[23]  = {0,1,2,3,4, 0,1,1,2,2,3,3,4, 0,1,1,2,2,2,3,3,4,4};
__constant__ int dPL3[23]  = {0,1,2,3,4, 1,0,2,1,3,2,4,3, 2,1,3,0,2,4,1,3,2,4};
__constant__ int dMOFF[24] = {0,1,10,35,84,165,168,171,186,201,236,271,334,
                              397,402,411,432,437,462,507,528,577,622,703};

// ---------------- CG table computation (double, matches reference) ----------------
__device__ double factd(int n) { double r = 1.0; for (int i = 2; i <= n; ++i) r *= (double)i; return r; }

__device__ double cgc(int l1, int l2, int l3, int m1, int m2, int m3) {
    if (m1 + m2 != m3) return 0.0;
    if (l3 < abs(l1 - l2) || l3 > l1 + l2) return 0.0;
    double pre = sqrt((double)(2 * l3 + 1) * factd(l3 + l1 - l2) * factd(l3 - l1 + l2) *
                      factd(l1 + l2 - l3) / factd(l1 + l2 + l3 + 1));
    pre *= sqrt(factd(l3 + m3) * factd(l3 - m3) * factd(l1 - m1) * factd(l1 + m1) *
                factd(l2 - m2) * factd(l2 + m2));
    double s = 0.0;
    for (int k = 0; k <= l1 + l2 - l3; ++k) {
        int a0 = k, a1 = l1 + l2 - l3 - k, a2 = l1 - m1 - k, a3 = l2 + m2 - k;
        int a4 = l3 - l2 + m1 + k, a5 = l3 - l1 - m2 + k;
        if (a0 < 0 || a1 < 0 || a2 < 0 || a3 < 0 || a4 < 0 || a5 < 0) continue;
        double d = factd(a0) * factd(a1) * factd(a2) * factd(a3) * factd(a4) * factd(a5);
        s += ((k & 1) ? -1.0 : 1.0) / d;
    }
    return pre * s;
}

__device__ void u_elem(int l, int a, int A, double& re, double& im) {
    re = 0.0; im = 0.0;
    const double is2 = 0.70710678118654752440;
    int mA = A - l, ma = a - l;
    if (mA == 0) { if (ma == 0) re = 1.0; return; }
    int m = mA > 0 ? mA : -mA;
    double sgn = (m & 1) ? -1.0 : 1.0;
    if (mA > 0) {
        if (ma == m)       re = sgn * is2;
        else if (ma == -m) re = is2;
    } else {
        if (ma == m)       im = sgn * is2;
        else if (ma == -m) im = -is2;
    }
}

__global__ void cg_init_kernel() {
    int p = blockIdx.x;
    int l1 = dPL1[p], l2 = dPL2[p], l3 = dPL3[p];
    int n1 = 2 * l1 + 1, n2 = 2 * l2 + 1, n3 = 2 * l3 + 1;
    int total = n1 * n2 * n3;
    for (int idx = threadIdx.x; idx < total; idx += blockDim.x) {
        int A  = idx / (n2 * n3);
        int rm = idx % (n2 * n3);
        int B  = rm / n3;
        int Cc = rm % n3;
        double acc = 0.0;
        for (int a = 0; a < n1; ++a) {
            double u1r, u1i; u_elem(l1, a, A, u1r, u1i);
            if (u1r == 0.0 && u1i == 0.0) continue;
            int m1 = a - l1;
            for (int b = 0; b < n2; ++b) {
                double u2r, u2i; u_elem(l2, b, B, u2r, u2i);
                if (u2r == 0.0 && u2i == 0.0) continue;
                int m2 = b - l2;
                int m3 = m1 + m2;
                if (m3 < -l3 || m3 > l3) continue;
                double cg = cgc(l1, l2, l3, m1, m2, m3);
                if (cg == 0.0) continue;
                int c = l3 + m3;
                double u3r, u3i; u_elem(l3, c, Cc, u3r, u3i);
                double pr = u1r * u2r - u1i * u2i;
                double pi = u1r * u2i + u1i * u2r;
                acc += cg * (pr * u3r + pi * u3i);
            }
        }
        g_C[p * 729 + A * 81 + B * 9 + Cc] = (float)acc;
    }
}

// ================= mma.sync helpers =================
__device__ __forceinline__ uint32_t smem_u32(const void* p) {
    uint32_t a;
    asm("{ .reg .u64 t; cvta.to.shared.u64 t, %1; cvt.u32.u64 %0, t; }" : "=r"(a) : "l"(p));
    return a;
}
__device__ __forceinline__ void ldm4(uint32_t addr, uint32_t& a0, uint32_t& a1,
                                     uint32_t& a2, uint32_t& a3) {
    asm volatile("ldmatrix.sync.aligned.m8n8.x4.shared.b16 {%0,%1,%2,%3}, [%4];"
                 : "=r"(a0), "=r"(a1), "=r"(a2), "=r"(a3) : "r"(addr));
}
__device__ __forceinline__ void mma16816(float* c,
                                         uint32_t a0, uint32_t a1, uint32_t a2, uint32_t a3,
                                         uint32_t b0, uint32_t b1) {
    asm volatile("mma.sync.aligned.m16n8k16.row.col.f32.bf16.bf16.f32 "
                 "{%0,%1,%2,%3}, {%4,%5,%6,%7}, {%8,%9}, {%0,%1,%2,%3};"
                 : "+f"(c[0]), "+f"(c[1]), "+f"(c[2]), "+f"(c[3])
                 : "r"(a0), "r"(a1), "r"(a2), "r"(a3), "r"(b0), "r"(b1));
}

// padded row-major bf16 tile: 128 rows x 128 cols, row stride 272 bytes (136 bf16)
#define ROWB 272
#define TILE_B (128 * ROWB)           // 34816 bytes per tile
#define TC_SMEM_BYTES (2 * TILE_B)    // A_hi, A_lo = 69632
#define WF_SMEM_BYTES (2 * TILE_B)

// ---------------- precompute B fragments (per weight matrix) ----------------
// mats 0-4: W1 l=0..4; 5-9: W2 l=0..4; 10-12: W3 l=0..2
__global__ __launch_bounds__(64) void wfrag_init(const float* __restrict__ W1,
                                                 const float* __restrict__ W2,
                                                 const float* __restrict__ W3) {
    extern __shared__ char smem[];
    char* sH = smem;
    char* sL = smem + TILE_B;
    const int mat = blockIdx.x;
    const float* __restrict__ W = (mat < 5) ? (W1 + (size_t)mat * NF * NF)
                               : (mat < 10) ? (W2 + (size_t)(mat - 5) * NF * NF)
                                            : (W3 + (size_t)(mat - 10) * NF * NF);
    const int tid = threadIdx.x;

    // stage W^T: Bt[n][k] = W[k][n], hi/lo split
    for (int t = 0; t < 64; ++t) {
        int pos = t * 64 + tid;                 // 4096 float4 slots
        int k = pos >> 5, n0 = (pos & 31) * 4;
        float4 w = *reinterpret_cast<const float4*>(W + (size_t)k * NF + n0);
        float wv[4] = {w.x, w.y, w.z, w.w};
#pragma unroll
        for (int q = 0; q < 4; ++q) {
            __nv_bfloat16 h  = __float2bfloat16_rn(wv[q]);
            __nv_bfloat16 lo = __float2bfloat16_rn(wv[q] - __bfloat162float(h));
            uint32_t off = (uint32_t)(n0 + q) * ROWB + (uint32_t)k * 2;
            *reinterpret_cast<unsigned short*>(sH + off) = reinterpret_cast<unsigned short&>(h);
            *reinterpret_cast<unsigned short*>(sL + off) = reinterpret_cast<unsigned short&>(lo);
        }
    }
    __syncthreads();

    const int wc = tid >> 5, lane = tid & 31;
    const int b_n = ((lane >> 4) & 1) * 8 + (lane & 7);
    const int b_k = ((lane >> 3) & 1) * 8;
    const uint32_t baseH = smem_u32(sH), baseL = smem_u32(sL);
    for (int kk = 0; kk < 8; ++kk) {
        for (int bt = 0; bt < 4; ++bt) {
            uint32_t boff = (uint32_t)(wc * 64 + bt * 16 + b_n) * ROWB +
                            (uint32_t)(kk * 16 + b_k) * 2;
            uint4 h, l;
            ldm4(baseH + boff, h.x, h.y, h.z, h.w);
            ldm4(baseL + boff, l.x, l.y, l.z, l.w);
            int idx = (((mat * 2 + wc) * 8 + kk) * 4 + bt) * 32 + lane;
            g_BfH[idx] = h;
            g_BfL[idx] = l;
        }
    }
}

// ================= GEMM: A from smem (ldmatrix), B fragments from global =================
// STAGE 0: X = desc[i]+desc[j] (gather fused), Y = g_y1, bias @ m==0
// STAGE 1: X = g_y1,  Y = g_y0 (+residual g_y1), bias @ m==0
// STAGE 2: X = g_rad, Y = g_v,  bias @ l==0
template <int STAGE>
__global__ __launch_bounds__(256, 2) void tc_gemm(const float* __restrict__ desc,
                                                  const int* __restrict__ nidx,
                                                  const float* __restrict__ bias) {
    extern __shared__ char smem[];
    char* sA_hi = smem;
    char* sA_lo = smem + TILE_B;
    float* Cs = reinterpret_cast<float*>(smem);   // reused after sync (128 x 132 floats)

    const int tid = threadIdx.x;
    const int wid = tid >> 5;
    const int lid = tid & 31;
    const int m = blockIdx.y;
    const int l = (STAGE == 2) ? m : ((m >= 16) ? 4 : (m >= 9) ? 3 : (m >= 4) ? 2 : (m >= 1) ? 1 : 0);
    const int mat = ((STAGE == 0) ? 0 : (STAGE == 1) ? 5 : 10) + l;
    const int e0 = blockIdx.x * 128;

    // ---- stage X into A_hi/A_lo ----
#pragma unroll
    for (int t = 0; t < 16; ++t) {
        int pos = t * 256 + tid;                // 4096 float4 slots
        int r = pos >> 5, k0 = (pos & 31) * 4;
        float4 x;
        if (STAGE == 0) {
            int e = e0 + r;
            int i = nidx[2 * e], j = nidx[2 * e + 1];
            float4 a = *reinterpret_cast<const float4*>(desc + ((size_t)i * NM + m) * NF + k0);
            float4 b = *reinterpret_cast<const float4*>(desc + ((size_t)j * NM + m) * NF + k0);
            x = make_float4(a.x + b.x, a.y + b.y, a.z + b.z, a.w + b.w);
        } else if (STAGE == 1) {
            x = *reinterpret_cast<const float4*>(g_y1 + ((size_t)(e0 + r) * NM + m) * NF + k0);
        } else {
            x = *reinterpret_cast<const float4*>(g_rad + (size_t)(e0 + r) * NF + k0);
        }
        __nv_bfloat162 h01 = __floats2bfloat162_rn(x.x, x.y);
        __nv_bfloat162 h23 = __floats2bfloat162_rn(x.z, x.w);
        __nv_bfloat162 l01 = __floats2bfloat162_rn(x.x - __bfloat162float(h01.x),
                                                   x.y - __bfloat162float(h01.y));
        __nv_bfloat162 l23 = __floats2bfloat162_rn(x.z - __bfloat162float(h23.x),
                                                   x.w - __bfloat162float(h23.y));
        uint32_t off = (uint32_t)r * ROWB + (uint32_t)k0 * 2;
        *reinterpret_cast<uint32_t*>(sA_hi + off)     = reinterpret_cast<uint32_t&>(h01);
        *reinterpret_cast<uint32_t*>(sA_hi + off + 4) = reinterpret_cast<uint32_t&>(h23);
        *reinterpret_cast<uint32_t*>(sA_lo + off)     = reinterpret_cast<uint32_t&>(l01);
        *reinterpret_cast<uint32_t*>(sA_lo + off + 4) = reinterpret_cast<uint32_t&>(l23);
    }
    __syncthreads();

    // ---- mainloop: A via ldmatrix (4/kstep), B fragments via LDG.128 (8/kstep) ----
    // warps: 4x2 grid; warp tile = 32 rows x 64 cols
    const int wr = wid >> 1;            // 0..3
    const int wc = wid & 1;             // 0..1
    const int r0 = wr * 32;

    const uint32_t aBaseHi = smem_u32(sA_hi);
    const uint32_t aBaseLo = smem_u32(sA_lo);
    const int a_r = lid & 15;
    const int a_k = (lid >> 4) * 8;

    const uint4* __restrict__ BfH = g_BfH + ((size_t)(mat * 2 + wc) * 8) * 128 + lid;
    const uint4* __restrict__ BfL = g_BfL + ((size_t)(mat * 2 + wc) * 8) * 128 + lid;

    float acc[16][4];
#pragma unroll
    for (int t = 0; t < 16; ++t)
#pragma unroll
        for (int q = 0; q < 4; ++q) acc[t][q] = 0.f;

#pragma unroll
    for (int kk = 0; kk < 8; ++kk) {
        uint32_t ah[2][4], al[2][4];
#pragma unroll
        for (int rt = 0; rt < 2; ++rt) {
            uint32_t aoff = (uint32_t)(r0 + rt * 16 + a_r) * ROWB + (uint32_t)(kk * 16 + a_k) * 2;
            ldm4(aBaseHi + aoff, ah[rt][0], ah[rt][1], ah[rt][2], ah[rt][3]);
            ldm4(aBaseLo + aoff, al[rt][0], al[rt][1], al[rt][2], al[rt][3]);
        }
#pragma unroll
        for (int bt = 0; bt < 4; ++bt) {
            uint4 bh = BfH[kk * 128 + bt * 32];
            uint4 bl = BfL[kk * 128 + bt * 32];
#pragma unroll
            for (int rt = 0; rt < 2; ++rt) {
                float* c0p = acc[rt * 8 + bt * 2];
                float* c1p = acc[rt * 8 + bt * 2 + 1];
                mma16816(c0p, ah[rt][0], ah[rt][1], ah[rt][2], ah[rt][3], bh.x, bh.y);
                mma16816(c1p, ah[rt][0], ah[rt][1], ah[rt][2], ah[rt][3], bh.z, bh.w);
                mma16816(c0p, ah[rt][0], ah[rt][1], ah[rt][2], ah[rt][3], bl.x, bl.y);
                mma16816(c1p, ah[rt][0], ah[rt][1], ah[rt][2], ah[rt][3], bl.z, bl.w);
                mma16816(c0p, al[rt][0], al[rt][1], al[rt][2], al[rt][3], bh.x, bh.y);
                mma16816(c1p, al[rt][0], al[rt][1], al[rt][2], al[rt][3], bh.z, bh.w);
            }
        }
    }
    __syncthreads();   // done reading A; safe to reuse as Cs

    // ---- write fragments to Cs (row stride 132 floats) ----
    const int c0 = wc * 64;
#pragma unroll
    for (int rt = 0; rt < 2; ++rt) {
#pragma unroll
        for (int nt = 0; nt < 8; ++nt) {
            float* a = acc[rt * 8 + nt];
            int rr = r0 + rt * 16 + (lid >> 2);
            int cc = c0 + nt * 8 + (lid & 3) * 2;
            *reinterpret_cast<float2*>(Cs + (size_t)rr * 132 + cc)       = make_float2(a[0], a[1]);
            *reinterpret_cast<float2*>(Cs + (size_t)(rr + 8) * 132 + cc) = make_float2(a[2], a[3]);
        }
    }
    __syncthreads();

    // ---- coalesced epilogue: bias, residual, store ----
    float* __restrict__ Y = (STAGE == 0) ? g_y1 : (STAGE == 1) ? g_y0 : g_v;
#pragma unroll
    for (int t = 0; t < 16; ++t) {
        int pos = t * 256 + tid;
        int r = pos >> 5, c4 = (pos & 31) * 4;
        float4 o = *reinterpret_cast<const float4*>(Cs + (size_t)r * 132 + c4);
        if (m == 0) {
            o.x += bias[c4]; o.y += bias[c4 + 1]; o.z += bias[c4 + 2]; o.w += bias[c4 + 3];
        }
        size_t obase = (STAGE == 2) ? (((size_t)(e0 + r) * 3 + m) * NF + c4)
                                    : (((size_t)(e0 + r) * NM + m) * NF + c4);
        if (STAGE == 1) {
            float4 rsd = *reinterpret_cast<const float4*>(g_y1 + obase);
            o.x += rsd.x; o.y += rsd.y; o.z += rsd.z; o.w += rsd.w;
        }
        *reinterpret_cast<float4*>(Y + obase) = o;
    }
}

// ---------------- normalize + gated mish (in place on g_y1) ----------------
__global__ __launch_bounds__(128) void norm_mish_kernel() {
    int e = blockIdx.x, f = threadIdx.x;
    size_t base = (size_t)e * (NM * NF) + f;
    float v[NM];
    float n2 = 0.f;
#pragma unroll
    for (int m = 0; m < NM; ++m) { v[m] = g_y1[base + (size_t)m * NF]; n2 += v[m] * v[m]; }
    float sc = rsqrtf(n2 + 1e-6f);
    float s = v[0] * sc;
    float sp = fmaxf(s, 0.f) + log1pf(expf(-fabsf(s)));
    float t = tanhf(sp);
    float sig = 1.f / (1.f + expf(-s));
    float dm = t + s * (1.f - t * t) * sig;
    g_y1[base] = s * t;
#pragma unroll
    for (int m = 1; m < NM; ++m) g_y1[base + (size_t)m * NF] = v[m] * sc * dm;
}

// ---------------- radial basis + spherical harmonics ----------------
__global__ __launch_bounds__(128) void radsh_kernel(const float* __restrict__ disp) {
    int e = blockIdx.x, f = threadIdx.x;
    float dx = disp[3 * e], dy = disp[3 * e + 1], dz = disp[3 * e + 2];
    float r = sqrtf(dx * dx + dy * dy + dz * dz + 1e-12f);
    float x = dx / r, y = dy / r, z = dz / r;
    float uc = r / 5.0f;
    float denom = fmaxf(1.f - uc * uc, 1e-9f);
    float cut = (uc < 1.f) ? expf(1.f - 1.f / denom) : 0.f;
    float ang = 3.14159265358979323846f * r / 5.0f;
    g_rad[(size_t)e * NF + f] = cosf((float)f * ang) * cut;
    if (f < 9) {
        const float s3 = 1.7320508075688772f;
        float shv;
        switch (f) {
            case 0: shv = 1.f; break;
            case 1: shv = y; break;
            case 2: shv = z; break;
            case 3: shv = x; break;
            case 4: shv = s3 * x * y; break;
            case 5: shv = s3 * y * z; break;
            case 6: shv = 0.5f * (3.f * z * z - 1.f); break;
            case 7: shv = s3 * x * z; break;
            default: shv = 0.5f * s3 * (x * x - y * y); break;
        }
        g_shg[(size_t)e * 9 + f] = shv;
    }
}

// ---------------- tensor product ----------------
template <int P, int L1, int L2, int L3, int MO>
__device__ __forceinline__ void tp_path(const float* __restrict__ wtp, int f,
                                        const float* __restrict__ Ms,
                                        const float (&vv)[3], const float (&yreg)[25],
                                        float (&acc)[25]) {
    float scale = wtp[P * NF + f] * vv[L1];
#pragma unroll
    for (int c = 0; c < 2 * L3 + 1; ++c) {
        float s = 0.f;
#pragma unroll
        for (int b = 0; b < 2 * L2 + 1; ++b)
            s += Ms[MO + b * (2 * L3 + 1) + c] * yreg[L2 * L2 + b];
        acc[L3 * L3 + c] += scale * s;
    }
}

__global__ __launch_bounds__(128) void tp_kernel(const float* __restrict__ wtp,
                                                 float* __restrict__ Out) {
    int e = blockIdx.x, f = threadIdx.x;
    __shared__ float Ms[703];
    __shared__ float shs[9];
    if (f < 9) shs[f] = g_shg[(size_t)e * 9 + f];
    __syncthreads();

    for (int idx = f; idx < 703; idx += 128) {
        int p = 0;
        while (dMOFF[p + 1] <= idx) ++p;
        int l1 = dPL1[p], l3 = dPL3[p];
        int local = idx - dMOFF[p];
        int n3 = 2 * l3 + 1;
        int b = local / n3, c = local - b * n3;
        const float* Cp = g_C + p * 729 + b * 9 + c;
        float s = 0.f;
        for (int a = 0; a <= 2 * l1; ++a) s += Cp[a * 81] * shs[l1 * l1 + a];
        Ms[idx] = s;
    }
    __syncthreads();

    float yreg[25];
    size_t base = (size_t)e * (NM * NF) + f;
#pragma unroll
    for (int m = 0; m < NM; ++m) yreg[m] = g_y0[base + (size_t)m * NF];
    float vv[3];
#pragma unroll
    for (int l = 0; l < 3; ++l) vv[l] = g_v[((size_t)e * 3 + l) * NF + f];
    float acc[25];
#pragma unroll
    for (int m = 0; m < NM; ++m) acc[m] = 0.f;

    tp_path<0, 0, 0, 0, 0>(wtp, f, Ms, vv, yreg, acc);
    tp_path<1, 0, 1, 1, 1>(wtp, f, Ms, vv, yreg, acc);
    tp_path<2, 0, 2, 2, 10>(wtp, f, Ms, vv, yreg, acc);
    tp_path<3, 0, 3, 3, 35>(wtp, f, Ms, vv, yreg, acc);
    tp_path<4, 0, 4, 4, 84>(wtp, f, Ms, vv, yreg, acc);
    tp_path<5, 1, 0, 1, 165>(wtp, f, Ms, vv, yreg, acc);
    tp_path<6, 1, 1, 0, 168>(wtp, f, Ms, vv, yreg, acc);
    tp_path<7, 1, 1, 2, 171>(wtp, f, Ms, vv, yreg, acc);
    tp_path<8, 1, 2, 1, 186>(wtp, f, Ms, vv, yreg, acc);
    tp_path<9, 1, 2, 3, 201>(wtp, f, Ms, vv, yreg, acc);
    tp_path<10, 1, 3, 2, 236>(wtp, f, Ms, vv, yreg, acc);
    tp_path<11, 1, 3, 4, 271>(wtp, f, Ms, vv, yreg, acc);
    tp_path<12, 1, 4, 3, 334>(wtp, f, Ms, vv, yreg, acc);
    tp_path<13, 2, 0, 2, 397>(wtp, f, Ms, vv, yreg, acc);
    tp_path<14, 2, 1, 1, 402>(wtp, f, Ms, vv, yreg, acc);
    tp_path<15, 2, 1, 3, 411>(wtp, f, Ms, vv, yreg, acc);
    tp_path<16, 2, 2, 0, 432>(wtp, f, Ms, vv, yreg, acc);
    tp_path<17, 2, 2, 2, 437>(wtp, f, Ms, vv, yreg, acc);
    tp_path<18, 2, 2, 4, 462>(wtp, f, Ms, vv, yreg, acc);
    tp_path<19, 2, 3, 1, 507>(wtp, f, Ms, vv, yreg, acc);
    tp_path<20, 2, 3, 3, 528>(wtp, f, Ms, vv, yreg, acc);
    tp_path<21, 2, 4, 2, 577>(wtp, f, Ms, vv, yreg, acc);
    tp_path<22, 2, 4, 4, 622>(wtp, f, Ms, vv, yreg, acc);

#pragma unroll
    for (int m = 0; m < NM; ++m) Out[base + (size_t)m * NF] = acc[m];
}

// ---------------- launch ----------------
extern "C" void kernel_launch(void* const* d_in, const int* in_sizes, int n_in,
                              void* d_out, int out_size) {
    const float* desc = (const float*)d_in[0];
    const int*   nidx = (const int*)d_in[1];
    const float* disp = (const float*)d_in[2];
    const float* W1   = (const float*)d_in[3];
    const float* b1   = (const float*)d_in[4];
    const float* W2   = (const float*)d_in[5];
    const float* b2   = (const float*)d_in[6];
    const float* W3   = (const float*)d_in[7];
    const float* b3   = (const float*)d_in[8];
    const float* wtp  = (const float*)d_in[9];
    float* out = (float*)d_out;
    (void)in_sizes; (void)n_in; (void)out_size;

    static int attr_set = 0;
    if (!attr_set) {
        cudaFuncSetAttribute(tc_gemm<0>, cudaFuncAttributeMaxDynamicSharedMemorySize, TC_SMEM_BYTES);
        cudaFuncSetAttribute(tc_gemm<1>, cudaFuncAttributeMaxDynamicSharedMemorySize, TC_SMEM_BYTES);
        cudaFuncSetAttribute(tc_gemm<2>, cudaFuncAttributeMaxDynamicSharedMemorySize, TC_SMEM_BYTES);
        cudaFuncSetAttribute(wfrag_init, cudaFuncAttributeMaxDynamicSharedMemorySize, WF_SMEM_BYTES);
        attr_set = 1;
    }

    cg_init_kernel<<<23, 128>>>();
    wfrag_init<<<13, 64, WF_SMEM_BYTES>>>(W1, W2, W3);
    tc_gemm<0><<<dim3(N_E / 128, NM), 256, TC_SMEM_BYTES>>>(desc, nidx, b1);
    norm_mish_kernel<<<N_E, 128>>>();
    tc_gemm<1><<<dim3(N_E / 128, NM), 256, TC_SMEM_BYTES>>>(desc, nidx, b2);
    radsh_kernel<<<N_E, 128>>>(disp);
    tc_gemm<2><<<dim3(N_E / 128, 3), 256, TC_SMEM_BYTES>>>(desc, nidx, b3);
    tp_kernel<<<N_E, 128>>>(wtp, out);
}